// round 12
// baseline (speedup 1.0000x reference)
#include <cuda_runtime.h>
#include <cstdint>

// Problem constants
#define Bn 16
#define Tn 2048
#define Cn 128
#define Hn 128

// Scratch: Q,K in [B][T][H] (H interleaved within 8-groups, tf32-rounded, Q pre-scaled),
// V transposed to [B][H][T] (T interleaved within 8-groups, tf32-rounded).
__device__ float g_Q[(size_t)Bn * Tn * Hn];
__device__ float g_K[(size_t)Bn * Tn * Hn];
__device__ float g_Vt[(size_t)Bn * Hn * Tn];

__device__ __forceinline__ uint32_t f2tf(float x) {
    uint32_t y;
    asm("cvt.rna.tf32.f32 %0, %1;" : "=r"(y) : "f"(x));
    return y;
}

__device__ __forceinline__ float fexp2(float x) {
    float y;
    asm("ex2.approx.f32 %0, %1;" : "=f"(y) : "f"(x));
    return y;
}

__device__ __forceinline__ void mma8(float* d,
                                     uint32_t a0, uint32_t a1, uint32_t a2, uint32_t a3,
                                     uint32_t b0, uint32_t b1) {
    asm volatile(
        "mma.sync.aligned.m16n8k8.row.col.f32.tf32.tf32.f32 "
        "{%0,%1,%2,%3},{%4,%5,%6,%7},{%8,%9},{%0,%1,%2,%3};"
        : "+f"(d[0]), "+f"(d[1]), "+f"(d[2]), "+f"(d[3])
        : "r"(a0), "r"(a1), "r"(a2), "r"(a3), "r"(b0), "r"(b1));
}

__device__ __forceinline__ void st4tf(float* d, float4 v) {
    d[0] = __uint_as_float(f2tf(v.x));
    d[1] = __uint_as_float(f2tf(v.y));
    d[2] = __uint_as_float(f2tf(v.z));
    d[3] = __uint_as_float(f2tf(v.w));
}

// cp.async helpers
__device__ __forceinline__ void cp16(uint32_t dst, const void* src) {
    asm volatile("cp.async.cg.shared.global [%0], [%1], 16;" :: "r"(dst), "l"(src) : "memory");
}
__device__ __forceinline__ void cpcommit() {
    asm volatile("cp.async.commit_group;" ::: "memory");
}
template <int N>
__device__ __forceinline__ void cpwait() {
    asm volatile("cp.async.wait_group %0;" :: "n"(N) : "memory");
}

// ============================================================================
// Projection: out[m,n] = sum_c x[m,c] * W[n,c]. M=32768, K=128, 3 Ws of N=128.
// Epilogues write the attention-ready layouts (tf32, interleaved, V transposed).
// ============================================================================
#define PROJ_SMEM ((128 * 132 + 64 * 132) * 4)

__global__ __launch_bounds__(256, 1) void proj_kernel(
    const float* __restrict__ x,
    const float* __restrict__ Wq,
    const float* __restrict__ Wk,
    const float* __restrict__ Wv) {
    extern __shared__ float sm[];
    float* sx = sm;               // [128][132] tf32
    float* sw = sm + 128 * 132;   // [64][132]  tf32

    const int tid = threadIdx.x;
    const int mt = blockIdx.x;
    const int wsel = blockIdx.y >> 1;
    const int nhalf = blockIdx.y & 1;
    const float* W = (wsel == 0) ? Wq : (wsel == 1 ? Wk : Wv);

    // Stage x tile [128,128] and W tile [64,128] as tf32
    const float* xg = x + (size_t)mt * 128 * Cn;
    for (int i = tid; i < 128 * 32; i += 256) {
        int r = i >> 5, c = (i & 31) << 2;
        st4tf(sx + r * 132 + c, *(const float4*)(xg + r * Cn + c));
    }
    const float* wg = W + (size_t)nhalf * 64 * Cn;
    for (int i = tid; i < 64 * 32; i += 256) {
        int r = i >> 5, c = (i & 31) << 2;
        st4tf(sw + r * 132 + c, *(const float4*)(wg + r * Cn + c));
    }
    __syncthreads();

    const int wid = tid >> 5, lane = tid & 31;
    const int gr = lane >> 2, gc = lane & 3;
    const int m0 = wid * 16;

    float acc[8][4];
#pragma unroll
    for (int i = 0; i < 8; i++) { acc[i][0] = acc[i][1] = acc[i][2] = acc[i][3] = 0.f; }

#pragma unroll
    for (int k0 = 0; k0 < 128; k0 += 8) {
        uint32_t a0 = __float_as_uint(sx[(m0 + gr) * 132 + k0 + gc]);
        uint32_t a1 = __float_as_uint(sx[(m0 + gr + 8) * 132 + k0 + gc]);
        uint32_t a2 = __float_as_uint(sx[(m0 + gr) * 132 + k0 + gc + 4]);
        uint32_t a3 = __float_as_uint(sx[(m0 + gr + 8) * 132 + k0 + gc + 4]);
#pragma unroll
        for (int nt = 0; nt < 8; nt++) {
            uint32_t b0 = __float_as_uint(sw[(nt * 8 + gr) * 132 + k0 + gc]);
            uint32_t b1 = __float_as_uint(sw[(nt * 8 + gr) * 132 + k0 + gc + 4]);
            mma8(acc[nt], a0, a1, a2, a3, b0, b1);
        }
    }

    if (wsel <= 1) {
        // Q/K: tf32-round (Q also scaled by C^-0.5), store H-interleaved:
        // within each 8-group, orig col j -> position 2*(j&3) + (j>>2).
        const float scale = (wsel == 0) ? 0.08838834764831845f : 1.0f;
        float* outp = (wsel == 0) ? g_Q : g_K;
        const int rbase = mt * 128 + m0;
        const int cb = nhalf * 64;
        const int pos = ((gc & 1) << 2) | (gc & 2);
#pragma unroll
        for (int nt = 0; nt < 8; nt++) {
            float q0 = __uint_as_float(f2tf(acc[nt][0] * scale));
            float q1 = __uint_as_float(f2tf(acc[nt][1] * scale));
            float q2 = __uint_as_float(f2tf(acc[nt][2] * scale));
            float q3 = __uint_as_float(f2tf(acc[nt][3] * scale));
            float r0 = __shfl_xor_sync(0xffffffffu, q0, 2);
            float r1 = __shfl_xor_sync(0xffffffffu, q1, 2);
            float r2 = __shfl_xor_sync(0xffffffffu, q2, 2);
            float r3 = __shfl_xor_sync(0xffffffffu, q3, 2);
            float2 lo = (gc < 2) ? make_float2(q0, r0) : make_float2(r1, q1);
            float2 hi = (gc < 2) ? make_float2(q2, r2) : make_float2(r3, q3);
            *(float2*)(outp + (size_t)(rbase + gr) * Hn + cb + nt * 8 + pos) = lo;
            *(float2*)(outp + (size_t)(rbase + gr + 8) * Hn + cb + nt * 8 + pos) = hi;
        }
    } else {
        // V: transpose through smem into g_Vt[b][h][t] with t interleaved.
        __syncthreads();
        float* tb = sm;  // reuse: [64 h-cols][132] holding t-major rows
        const int pgr = 2 * (gr & 3) + (gr >> 2);
#pragma unroll
        for (int nt = 0; nt < 8; nt++) {
            int c = nt * 8 + 2 * gc;
            tb[c * 132 + m0 + pgr]           = __uint_as_float(f2tf(acc[nt][0]));
            tb[(c + 1) * 132 + m0 + pgr]     = __uint_as_float(f2tf(acc[nt][1]));
            tb[c * 132 + m0 + 8 + pgr]       = __uint_as_float(f2tf(acc[nt][2]));
            tb[(c + 1) * 132 + m0 + 8 + pgr] = __uint_as_float(f2tf(acc[nt][3]));
        }
        __syncthreads();
        const int bb = mt >> 4;
        const int t0 = (mt & 15) * 128;
        for (int i = tid; i < 64 * 32; i += 256) {
            int col = i >> 5, c4 = i & 31;
            float4 v = *(const float4*)(tb + col * 132 + c4 * 4);
            *(float4*)(g_Vt + ((size_t)bb * Hn + nhalf * 64 + col) * Tn + t0 + c4 * 4) = v;
        }
    }
}

// ============================================================================
// Flash attention. Block = (q-tile 128, batch), 256 threads / 8 warps.
// All staging via cp.async (operands already tf32 + frag-interleaved in gmem):
//   sQ [128][136], sK 2x[64][136] (double-buffered), sVt [128][72] (V^T),
//   sP per-warp [16][68]. LDS.64 frag loads, bank-conflict-free.
// ============================================================================
#define SQ_OFF 0
#define SK_OFF 17408
#define SK_SZ 8704
#define SV_OFF 34816
#define SP_OFF 44032
#define ATTN_WORDS 52736
#define ATTN_SMEM (ATTN_WORDS * 4)

__device__ __forceinline__ void k_stage(uint32_t smb, const float* Kg, int buf, int kt, int tid) {
    const float* src = Kg + (size_t)kt * 64 * Hn;
    uint32_t base = smb + (uint32_t)((SK_OFF + buf * SK_SZ) * 4);
#pragma unroll
    for (int i = 0; i < 8; i++) {
        int idx = tid + i * 256;
        int r = idx >> 5, c4 = idx & 31;
        cp16(base + (uint32_t)((r * 136 + c4 * 4) * 4), src + r * Hn + c4 * 4);
    }
}

__device__ __forceinline__ void v_stage(uint32_t smb, const float* Vg, int kt, int tid) {
    const float* src = Vg + kt * 64;
    uint32_t base = smb + (uint32_t)(SV_OFF * 4);
#pragma unroll
    for (int i = 0; i < 8; i++) {
        int idx = tid + i * 256;
        int h = idx >> 4, c4 = idx & 15;
        cp16(base + (uint32_t)((h * 72 + c4 * 4) * 4), src + (size_t)h * Tn + c4 * 4);
    }
}

__global__ __launch_bounds__(256, 1) void attn_kernel(float* __restrict__ out) {
    extern __shared__ float sm[];
    const uint32_t smb = (uint32_t)__cvta_generic_to_shared(sm);

    const int tid = threadIdx.x;
    const int wid = tid >> 5, lane = tid & 31;
    const int gr = lane >> 2, gc = lane & 3;
    const int qi = 15 - (int)blockIdx.x;  // heavy tiles first (LPT)
    const int b = blockIdx.y;

    const float* Qg = g_Q + ((size_t)b * Tn + (size_t)qi * 128) * Hn;
    const float* Kg = g_K + (size_t)b * Tn * Hn;
    const float* Vg = g_Vt + (size_t)b * Hn * Tn;
    const float L2E = 1.4426950408889634f;

    // Prologue: async-stage Q, K0, V0 (three groups)
#pragma unroll
    for (int i = 0; i < 16; i++) {
        int idx = tid + i * 256;
        int r = idx >> 5, c4 = idx & 31;
        cp16(smb + (uint32_t)((r * 136 + c4 * 4) * 4), Qg + r * Hn + c4 * 4);
    }
    cpcommit();
    k_stage(smb, Kg, 0, 0, tid);
    cpcommit();
    v_stage(smb, Vg, 0, tid);
    cpcommit();

    float o[16][4];
#pragma unroll
    for (int i = 0; i < 16; i++) { o[i][0] = o[i][1] = o[i][2] = o[i][3] = 0.f; }
    float mrow[2] = {-1e30f, -1e30f};
    float lrow[2] = {0.f, 0.f};
    const int m0 = wid * 16;
    const int nkt = 2 * qi + 2;

    const float* sQ = sm + SQ_OFF;
    const float* sV = sm + SV_OFF;
    float* pw = sm + SP_OFF + wid * 16 * 68;

    for (int kj = 0; kj < nkt; kj++) {
        // Prefetch next K tile (whole iteration of overlap)
        if (kj + 1 < nkt) k_stage(smb, Kg, (kj + 1) & 1, kj + 1, tid);
        cpcommit();
        cpwait<2>();  // K_kj (and Q on first iter) complete; V_kj + K_{kj+1} may pend
        __syncthreads();

        const float* sK = sm + SK_OFF + (kj & 1) * SK_SZ;

        // S = Q * K^T (warp: 16 x 64), LDS.64 frag loads
        float s[8][4];
#pragma unroll
        for (int i = 0; i < 8; i++) { s[i][0] = s[i][1] = s[i][2] = s[i][3] = 0.f; }
#pragma unroll
        for (int k0 = 0; k0 < 128; k0 += 8) {
            float2 aA = *(const float2*)(sQ + (m0 + gr) * 136 + k0 + 2 * gc);      // {a0,a2}
            float2 aB = *(const float2*)(sQ + (m0 + gr + 8) * 136 + k0 + 2 * gc);  // {a1,a3}
            uint32_t a0 = __float_as_uint(aA.x), a2 = __float_as_uint(aA.y);
            uint32_t a1 = __float_as_uint(aB.x), a3 = __float_as_uint(aB.y);
#pragma unroll
            for (int nt = 0; nt < 8; nt++) {
                float2 bb = *(const float2*)(sK + (nt * 8 + gr) * 136 + k0 + 2 * gc);
                mma8(s[nt], a0, a1, a2, a3, __float_as_uint(bb.x), __float_as_uint(bb.y));
            }
        }

        // Causal mask on the two diagonal tiles
        if (kj >= 2 * qi) {
            const int q0 = qi * 128 + m0 + gr;
#pragma unroll
            for (int nt = 0; nt < 8; nt++) {
                int cg = kj * 64 + nt * 8 + 2 * gc;
                if (cg > q0)         s[nt][0] = -1e30f;
                if (cg + 1 > q0)     s[nt][1] = -1e30f;
                if (cg > q0 + 8)     s[nt][2] = -1e30f;
                if (cg + 1 > q0 + 8) s[nt][3] = -1e30f;
            }
        }

        // Online softmax
#pragma unroll
        for (int h = 0; h < 2; h++) {
            float rm = -1e30f;
#pragma unroll
            for (int nt = 0; nt < 8; nt++)
                rm = fmaxf(rm, fmaxf(s[nt][2 * h], s[nt][2 * h + 1]));
            rm = fmaxf(rm, __shfl_xor_sync(0xffffffffu, rm, 1));
            rm = fmaxf(rm, __shfl_xor_sync(0xffffffffu, rm, 2));
            float mn = fmaxf(mrow[h], rm);
            float alpha = fexp2((mrow[h] - mn) * L2E);
            mrow[h] = mn;
            float rs = 0.f;
#pragma unroll
            for (int nt = 0; nt < 8; nt++) {
                float p0 = fexp2((s[nt][2 * h] - mn) * L2E);
                float p1 = fexp2((s[nt][2 * h + 1] - mn) * L2E);
                s[nt][2 * h] = p0;
                s[nt][2 * h + 1] = p1;
                rs += p0 + p1;
            }
            rs += __shfl_xor_sync(0xffffffffu, rs, 1);
            rs += __shfl_xor_sync(0xffffffffu, rs, 2);
            lrow[h] = lrow[h] * alpha + rs;
#pragma unroll
            for (int ht = 0; ht < 16; ht++) {
                o[ht][2 * h] *= alpha;
                o[ht][2 * h + 1] *= alpha;
            }
        }

        // P relayout through per-warp smem (tf32)
#pragma unroll
        for (int nt = 0; nt < 8; nt++) {
            int c = nt * 8 + 2 * gc;
            pw[gr * 68 + c]           = __uint_as_float(f2tf(s[nt][0]));
            pw[gr * 68 + c + 1]       = __uint_as_float(f2tf(s[nt][1]));
            pw[(gr + 8) * 68 + c]     = __uint_as_float(f2tf(s[nt][2]));
            pw[(gr + 8) * 68 + c + 1] = __uint_as_float(f2tf(s[nt][3]));
        }
        __syncwarp();

        cpwait<1>();  // V_kj complete; K_{kj+1} may still be in flight
        __syncthreads();

        // O += P * V  (V^T in smem: row = h, cols = interleaved keys -> LDS.64)
#pragma unroll
        for (int s0 = 0; s0 < 64; s0 += 8) {
            uint32_t a0 = __float_as_uint(pw[gr * 68 + s0 + gc]);
            uint32_t a1 = __float_as_uint(pw[(gr + 8) * 68 + s0 + gc]);
            uint32_t a2 = __float_as_uint(pw[gr * 68 + s0 + gc + 4]);
            uint32_t a3 = __float_as_uint(pw[(gr + 8) * 68 + s0 + gc + 4]);
#pragma unroll
            for (int ht = 0; ht < 16; ht++) {
                float2 bb = *(const float2*)(sV + (ht * 8 + gr) * 72 + s0 + 2 * gc);
                mma8(o[ht], a0, a1, a2, a3, __float_as_uint(bb.x), __float_as_uint(bb.y));
            }
        }
        __syncthreads();  // all warps done reading sV before refill

        if (kj + 1 < nkt) v_stage(smb, Vg, kj + 1, tid);
        cpcommit();  // V_{kj+1}; overlaps next iteration's S phase
    }

    // Epilogue: normalize and store
    const float i0 = 1.f / lrow[0];
    const float i1 = 1.f / lrow[1];
    const int r0 = qi * 128 + m0 + gr;
    float* og = out + (size_t)b * Tn * Hn;
#pragma unroll
    for (int ht = 0; ht < 16; ht++) {
        int col = ht * 8 + 2 * gc;
        *(float2*)(og + (size_t)r0 * Hn + col) =
            make_float2(o[ht][0] * i0, o[ht][1] * i0);
        *(float2*)(og + (size_t)(r0 + 8) * Hn + col) =
            make_float2(o[ht][2] * i1, o[ht][3] * i1);
    }
}

extern "C" void kernel_launch(void* const* d_in, const int* in_sizes, int n_in,
                              void* d_out, int out_size) {
    const float* x = (const float*)d_in[0];
    const float* Wq = (const float*)d_in[1];
    const float* Wk = (const float*)d_in[2];
    const float* Wv = (const float*)d_in[3];

    cudaFuncSetAttribute(proj_kernel, cudaFuncAttributeMaxDynamicSharedMemorySize, PROJ_SMEM);
    cudaFuncSetAttribute(attn_kernel, cudaFuncAttributeMaxDynamicSharedMemorySize, ATTN_SMEM);

    proj_kernel<<<dim3(256, 6), 256, PROJ_SMEM>>>(x, Wq, Wk, Wv);
    attn_kernel<<<dim3(16, 16), 256, ATTN_SMEM>>>((float*)d_out);
}

// round 13
// speedup vs baseline: 1.0021x; 1.0021x over previous
#include <cuda_runtime.h>
#include <cstdint>

// Problem constants
#define Bn 16
#define Tn 2048
#define Cn 128
#define Hn 128

// Scratch: Q,K in [B][T][H] (H interleaved within 8-groups, tf32-rounded, Q pre-scaled),
// V transposed to [B][H][T] (T interleaved within 8-groups, tf32-rounded).
__device__ float g_Q[(size_t)Bn * Tn * Hn];
__device__ float g_K[(size_t)Bn * Tn * Hn];
__device__ float g_Vt[(size_t)Bn * Hn * Tn];

__device__ __forceinline__ uint32_t f2tf(float x) {
    uint32_t y;
    asm("cvt.rna.tf32.f32 %0, %1;" : "=r"(y) : "f"(x));
    return y;
}

__device__ __forceinline__ float fexp2(float x) {
    float y;
    asm("ex2.approx.f32 %0, %1;" : "=f"(y) : "f"(x));
    return y;
}

__device__ __forceinline__ void mma8(float* d,
                                     uint32_t a0, uint32_t a1, uint32_t a2, uint32_t a3,
                                     uint32_t b0, uint32_t b1) {
    asm volatile(
        "mma.sync.aligned.m16n8k8.row.col.f32.tf32.tf32.f32 "
        "{%0,%1,%2,%3},{%4,%5,%6,%7},{%8,%9},{%0,%1,%2,%3};"
        : "+f"(d[0]), "+f"(d[1]), "+f"(d[2]), "+f"(d[3])
        : "r"(a0), "r"(a1), "r"(a2), "r"(a3), "r"(b0), "r"(b1));
}

__device__ __forceinline__ void st4tf(float* d, float4 v) {
    d[0] = __uint_as_float(f2tf(v.x));
    d[1] = __uint_as_float(f2tf(v.y));
    d[2] = __uint_as_float(f2tf(v.z));
    d[3] = __uint_as_float(f2tf(v.w));
}

// cp.async helpers
__device__ __forceinline__ void cp16(uint32_t dst, const void* src) {
    asm volatile("cp.async.cg.shared.global [%0], [%1], 16;" :: "r"(dst), "l"(src) : "memory");
}
__device__ __forceinline__ void cpcommit() {
    asm volatile("cp.async.commit_group;" ::: "memory");
}
template <int N>
__device__ __forceinline__ void cpwait() {
    asm volatile("cp.async.wait_group %0;" :: "n"(N) : "memory");
}

// ============================================================================
// Projection: out[m,n] = sum_c x[m,c] * W[n,c]. M=32768, K=128, 3 Ws of N=128.
// Epilogues write the attention-ready layouts (tf32, interleaved, V transposed).
// ============================================================================
#define PROJ_SMEM ((128 * 132 + 64 * 132) * 4)

__global__ __launch_bounds__(256, 1) void proj_kernel(
    const float* __restrict__ x,
    const float* __restrict__ Wq,
    const float* __restrict__ Wk,
    const float* __restrict__ Wv) {
    extern __shared__ float sm[];
    float* sx = sm;               // [128][132] tf32
    float* sw = sm + 128 * 132;   // [64][132]  tf32

    const int tid = threadIdx.x;
    const int mt = blockIdx.x;
    const int wsel = blockIdx.y >> 1;
    const int nhalf = blockIdx.y & 1;
    const float* W = (wsel == 0) ? Wq : (wsel == 1 ? Wk : Wv);

    // Stage x tile [128,128] and W tile [64,128] as tf32
    const float* xg = x + (size_t)mt * 128 * Cn;
    for (int i = tid; i < 128 * 32; i += 256) {
        int r = i >> 5, c = (i & 31) << 2;
        st4tf(sx + r * 132 + c, *(const float4*)(xg + r * Cn + c));
    }
    const float* wg = W + (size_t)nhalf * 64 * Cn;
    for (int i = tid; i < 64 * 32; i += 256) {
        int r = i >> 5, c = (i & 31) << 2;
        st4tf(sw + r * 132 + c, *(const float4*)(wg + r * Cn + c));
    }
    __syncthreads();

    const int wid = tid >> 5, lane = tid & 31;
    const int gr = lane >> 2, gc = lane & 3;
    const int m0 = wid * 16;

    float acc[8][4];
#pragma unroll
    for (int i = 0; i < 8; i++) { acc[i][0] = acc[i][1] = acc[i][2] = acc[i][3] = 0.f; }

#pragma unroll
    for (int k0 = 0; k0 < 128; k0 += 8) {
        uint32_t a0 = __float_as_uint(sx[(m0 + gr) * 132 + k0 + gc]);
        uint32_t a1 = __float_as_uint(sx[(m0 + gr + 8) * 132 + k0 + gc]);
        uint32_t a2 = __float_as_uint(sx[(m0 + gr) * 132 + k0 + gc + 4]);
        uint32_t a3 = __float_as_uint(sx[(m0 + gr + 8) * 132 + k0 + gc + 4]);
#pragma unroll
        for (int nt = 0; nt < 8; nt++) {
            uint32_t b0 = __float_as_uint(sw[(nt * 8 + gr) * 132 + k0 + gc]);
            uint32_t b1 = __float_as_uint(sw[(nt * 8 + gr) * 132 + k0 + gc + 4]);
            mma8(acc[nt], a0, a1, a2, a3, b0, b1);
        }
    }

    if (wsel <= 1) {
        // Q/K: tf32-round (Q also scaled by C^-0.5), store H-interleaved:
        // within each 8-group, orig col j -> position 2*(j&3) + (j>>2).
        const float scale = (wsel == 0) ? 0.08838834764831845f : 1.0f;
        float* outp = (wsel == 0) ? g_Q : g_K;
        const int rbase = mt * 128 + m0;
        const int cb = nhalf * 64;
        const int pos = ((gc & 1) << 2) | (gc & 2);
#pragma unroll
        for (int nt = 0; nt < 8; nt++) {
            float q0 = __uint_as_float(f2tf(acc[nt][0] * scale));
            float q1 = __uint_as_float(f2tf(acc[nt][1] * scale));
            float q2 = __uint_as_float(f2tf(acc[nt][2] * scale));
            float q3 = __uint_as_float(f2tf(acc[nt][3] * scale));
            float r0 = __shfl_xor_sync(0xffffffffu, q0, 2);
            float r1 = __shfl_xor_sync(0xffffffffu, q1, 2);
            float r2 = __shfl_xor_sync(0xffffffffu, q2, 2);
            float r3 = __shfl_xor_sync(0xffffffffu, q3, 2);
            float2 lo = (gc < 2) ? make_float2(q0, r0) : make_float2(r1, q1);
            float2 hi = (gc < 2) ? make_float2(q2, r2) : make_float2(r3, q3);
            *(float2*)(outp + (size_t)(rbase + gr) * Hn + cb + nt * 8 + pos) = lo;
            *(float2*)(outp + (size_t)(rbase + gr + 8) * Hn + cb + nt * 8 + pos) = hi;
        }
    } else {
        // V: transpose through smem into g_Vt[b][h][t] with t interleaved.
        __syncthreads();
        float* tb = sm;  // reuse: [64 h-cols][132] holding t-major rows
        const int pgr = 2 * (gr & 3) + (gr >> 2);
#pragma unroll
        for (int nt = 0; nt < 8; nt++) {
            int c = nt * 8 + 2 * gc;
            tb[c * 132 + m0 + pgr]           = __uint_as_float(f2tf(acc[nt][0]));
            tb[(c + 1) * 132 + m0 + pgr]     = __uint_as_float(f2tf(acc[nt][1]));
            tb[c * 132 + m0 + 8 + pgr]       = __uint_as_float(f2tf(acc[nt][2]));
            tb[(c + 1) * 132 + m0 + 8 + pgr] = __uint_as_float(f2tf(acc[nt][3]));
        }
        __syncthreads();
        const int bb = mt >> 4;
        const int t0 = (mt & 15) * 128;
        for (int i = tid; i < 64 * 32; i += 256) {
            int col = i >> 5, c4 = i & 31;
            float4 v = *(const float4*)(tb + col * 132 + c4 * 4);
            *(float4*)(g_Vt + ((size_t)bb * Hn + nhalf * 64 + col) * Tn + t0 + c4 * 4) = v;
        }
    }
}

// ============================================================================
// Flash attention. Block = (q-tile 128, batch), 256 threads / 8 warps.
// All staging via cp.async (operands already tf32 + frag-interleaved in gmem):
//   sQ [128][136], sK 2x[64][136] (double-buffered), sVt [128][72] (V^T),
//   sP per-warp [16][68]. LDS.64 frag loads, bank-conflict-free.
// ============================================================================
#define SQ_OFF 0
#define SK_OFF 17408
#define SK_SZ 8704
#define SV_OFF 34816
#define SP_OFF 44032
#define ATTN_WORDS 52736
#define ATTN_SMEM (ATTN_WORDS * 4)

__device__ __forceinline__ void k_stage(uint32_t smb, const float* Kg, int buf, int kt, int tid) {
    const float* src = Kg + (size_t)kt * 64 * Hn;
    uint32_t base = smb + (uint32_t)((SK_OFF + buf * SK_SZ) * 4);
#pragma unroll
    for (int i = 0; i < 8; i++) {
        int idx = tid + i * 256;
        int r = idx >> 5, c4 = idx & 31;
        cp16(base + (uint32_t)((r * 136 + c4 * 4) * 4), src + r * Hn + c4 * 4);
    }
}

__device__ __forceinline__ void v_stage(uint32_t smb, const float* Vg, int kt, int tid) {
    const float* src = Vg + kt * 64;
    uint32_t base = smb + (uint32_t)(SV_OFF * 4);
#pragma unroll
    for (int i = 0; i < 8; i++) {
        int idx = tid + i * 256;
        int h = idx >> 4, c4 = idx & 15;
        cp16(base + (uint32_t)((h * 72 + c4 * 4) * 4), src + (size_t)h * Tn + c4 * 4);
    }
}

__global__ __launch_bounds__(256, 1) void attn_kernel(float* __restrict__ out) {
    extern __shared__ float sm[];
    const uint32_t smb = (uint32_t)__cvta_generic_to_shared(sm);

    const int tid = threadIdx.x;
    const int wid = tid >> 5, lane = tid & 31;
    const int gr = lane >> 2, gc = lane & 3;
    const int qi = 15 - (int)blockIdx.x;  // heavy tiles first (LPT)
    const int b = blockIdx.y;

    const float* Qg = g_Q + ((size_t)b * Tn + (size_t)qi * 128) * Hn;
    const float* Kg = g_K + (size_t)b * Tn * Hn;
    const float* Vg = g_Vt + (size_t)b * Hn * Tn;
    const float L2E = 1.4426950408889634f;

    // Prologue: async-stage Q, K0, V0 (three groups)
#pragma unroll
    for (int i = 0; i < 16; i++) {
        int idx = tid + i * 256;
        int r = idx >> 5, c4 = idx & 31;
        cp16(smb + (uint32_t)((r * 136 + c4 * 4) * 4), Qg + r * Hn + c4 * 4);
    }
    cpcommit();
    k_stage(smb, Kg, 0, 0, tid);
    cpcommit();
    v_stage(smb, Vg, 0, tid);
    cpcommit();

    float o[16][4];
#pragma unroll
    for (int i = 0; i < 16; i++) { o[i][0] = o[i][1] = o[i][2] = o[i][3] = 0.f; }
    float mrow[2] = {-1e30f, -1e30f};
    float lrow[2] = {0.f, 0.f};
    const int m0 = wid * 16;
    const int nkt = 2 * qi + 2;

    const float* sQ = sm + SQ_OFF;
    const float* sV = sm + SV_OFF;
    float* pw = sm + SP_OFF + wid * 16 * 68;

    for (int kj = 0; kj < nkt; kj++) {
        // Prefetch next K tile (whole iteration of overlap)
        if (kj + 1 < nkt) k_stage(smb, Kg, (kj + 1) & 1, kj + 1, tid);
        cpcommit();
        cpwait<2>();  // K_kj (and Q on first iter) complete; V_kj + K_{kj+1} may pend
        __syncthreads();

        const float* sK = sm + SK_OFF + (kj & 1) * SK_SZ;

        // S = Q * K^T (warp: 16 x 64), LDS.64 frag loads
        float s[8][4];
#pragma unroll
        for (int i = 0; i < 8; i++) { s[i][0] = s[i][1] = s[i][2] = s[i][3] = 0.f; }
#pragma unroll
        for (int k0 = 0; k0 < 128; k0 += 8) {
            float2 aA = *(const float2*)(sQ + (m0 + gr) * 136 + k0 + 2 * gc);      // {a0,a2}
            float2 aB = *(const float2*)(sQ + (m0 + gr + 8) * 136 + k0 + 2 * gc);  // {a1,a3}
            uint32_t a0 = __float_as_uint(aA.x), a2 = __float_as_uint(aA.y);
            uint32_t a1 = __float_as_uint(aB.x), a3 = __float_as_uint(aB.y);
#pragma unroll
            for (int nt = 0; nt < 8; nt++) {
                float2 bb = *(const float2*)(sK + (nt * 8 + gr) * 136 + k0 + 2 * gc);
                mma8(s[nt], a0, a1, a2, a3, __float_as_uint(bb.x), __float_as_uint(bb.y));
            }
        }

        // Causal mask on the two diagonal tiles
        if (kj >= 2 * qi) {
            const int q0 = qi * 128 + m0 + gr;
#pragma unroll
            for (int nt = 0; nt < 8; nt++) {
                int cg = kj * 64 + nt * 8 + 2 * gc;
                if (cg > q0)         s[nt][0] = -1e30f;
                if (cg + 1 > q0)     s[nt][1] = -1e30f;
                if (cg > q0 + 8)     s[nt][2] = -1e30f;
                if (cg + 1 > q0 + 8) s[nt][3] = -1e30f;
            }
        }

        // Online softmax
#pragma unroll
        for (int h = 0; h < 2; h++) {
            float rm = -1e30f;
#pragma unroll
            for (int nt = 0; nt < 8; nt++)
                rm = fmaxf(rm, fmaxf(s[nt][2 * h], s[nt][2 * h + 1]));
            rm = fmaxf(rm, __shfl_xor_sync(0xffffffffu, rm, 1));
            rm = fmaxf(rm, __shfl_xor_sync(0xffffffffu, rm, 2));
            float mn = fmaxf(mrow[h], rm);
            float alpha = fexp2((mrow[h] - mn) * L2E);
            mrow[h] = mn;
            float rs = 0.f;
#pragma unroll
            for (int nt = 0; nt < 8; nt++) {
                float p0 = fexp2((s[nt][2 * h] - mn) * L2E);
                float p1 = fexp2((s[nt][2 * h + 1] - mn) * L2E);
                s[nt][2 * h] = p0;
                s[nt][2 * h + 1] = p1;
                rs += p0 + p1;
            }
            rs += __shfl_xor_sync(0xffffffffu, rs, 1);
            rs += __shfl_xor_sync(0xffffffffu, rs, 2);
            lrow[h] = lrow[h] * alpha + rs;
#pragma unroll
            for (int ht = 0; ht < 16; ht++) {
                o[ht][2 * h] *= alpha;
                o[ht][2 * h + 1] *= alpha;
            }
        }

        // P relayout through per-warp smem (tf32)
#pragma unroll
        for (int nt = 0; nt < 8; nt++) {
            int c = nt * 8 + 2 * gc;
            pw[gr * 68 + c]           = __uint_as_float(f2tf(s[nt][0]));
            pw[gr * 68 + c + 1]       = __uint_as_float(f2tf(s[nt][1]));
            pw[(gr + 8) * 68 + c]     = __uint_as_float(f2tf(s[nt][2]));
            pw[(gr + 8) * 68 + c + 1] = __uint_as_float(f2tf(s[nt][3]));
        }
        __syncwarp();

        cpwait<1>();  // V_kj complete; K_{kj+1} may still be in flight
        __syncthreads();

        // O += P * V  (V^T in smem: row = h, cols = interleaved keys -> LDS.64)
#pragma unroll
        for (int s0 = 0; s0 < 64; s0 += 8) {
            uint32_t a0 = __float_as_uint(pw[gr * 68 + s0 + gc]);
            uint32_t a1 = __float_as_uint(pw[(gr + 8) * 68 + s0 + gc]);
            uint32_t a2 = __float_as_uint(pw[gr * 68 + s0 + gc + 4]);
            uint32_t a3 = __float_as_uint(pw[(gr + 8) * 68 + s0 + gc + 4]);
#pragma unroll
            for (int ht = 0; ht < 16; ht++) {
                float2 bb = *(const float2*)(sV + (ht * 8 + gr) * 72 + s0 + 2 * gc);
                mma8(o[ht], a0, a1, a2, a3, __float_as_uint(bb.x), __float_as_uint(bb.y));
            }
        }
        __syncthreads();  // all warps done reading sV before refill

        if (kj + 1 < nkt) v_stage(smb, Vg, kj + 1, tid);
        cpcommit();  // V_{kj+1}; overlaps next iteration's S phase
    }

    // Epilogue: normalize and store
    const float i0 = 1.f / lrow[0];
    const float i1 = 1.f / lrow[1];
    const int r0 = qi * 128 + m0 + gr;
    float* og = out + (size_t)b * Tn * Hn;
#pragma unroll
    for (int ht = 0; ht < 16; ht++) {
        int col = ht * 8 + 2 * gc;
        *(float2*)(og + (size_t)r0 * Hn + col) =
            make_float2(o[ht][0] * i0, o[ht][1] * i0);
        *(float2*)(og + (size_t)(r0 + 8) * Hn + col) =
            make_float2(o[ht][2] * i1, o[ht][3] * i1);
    }
}

extern "C" void kernel_launch(void* const* d_in, const int* in_sizes, int n_in,
                              void* d_out, int out_size) {
    const float* x = (const float*)d_in[0];
    const float* Wq = (const float*)d_in[1];
    const float* Wk = (const float*)d_in[2];
    const float* Wv = (const float*)d_in[3];

    cudaFuncSetAttribute(proj_kernel, cudaFuncAttributeMaxDynamicSharedMemorySize, PROJ_SMEM);
    cudaFuncSetAttribute(attn_kernel, cudaFuncAttributeMaxDynamicSharedMemorySize, ATTN_SMEM);

    proj_kernel<<<dim3(256, 6), 256, PROJ_SMEM>>>(x, Wq, Wk, Wv);
    attn_kernel<<<dim3(16, 16), 256, ATTN_SMEM>>>((float*)d_out);
}